// round 3
// baseline (speedup 1.0000x reference)
#include <cuda_runtime.h>
#include <cstdint>

// B=8,R=32 -> 8192 points; E=8 groups; L=16 levels; F=4; T=2^17
// MLP 64->64->64->32, leaky_relu(0.2)
// Cooperative layout: 256 threads / 64 points per block; 4 threads per point.
// Single activation buffer reused across layers (read -> barrier -> write).

#define TMASK 0x1FFFFu
#define TSIZE (1u << 17)
#define PTS   64            // points per block
#define STR   68            // padded row stride (floats); 16B aligned, conflict-free

// shared layout in floats
#define OFF_W1 0                      // 64*64
#define OFF_W2 4096                   // 64*64
#define OFF_W3 8192                   // 64*32
#define OFF_B1 10240                  // 64
#define OFF_B2 10304                  // 64
#define OFF_B3 10368                  // 32
#define OFF_F  10400                  // PTS*STR (feats / h1 / h2, reused)
#define SMEM_FLOATS (OFF_F + PTS*STR) // 14752 floats = 59008 B

__constant__ float c_res[16] = {16.f,16.f,17.f,18.f,19.f,20.f,21.f,22.f,
                                23.f,24.f,25.f,26.f,27.f,29.f,30.f,32.f};

__device__ __forceinline__ float lrelu(float v) { return v > 0.f ? v : 0.2f * v; }

__device__ __forceinline__ float4 f4fma(float a, float4 w, float4 acc) {
    acc.x = fmaf(a, w.x, acc.x);
    acc.y = fmaf(a, w.y, acc.y);
    acc.z = fmaf(a, w.z, acc.z);
    acc.w = fmaf(a, w.w, acc.w);
    return acc;
}

extern __shared__ float smem[];

__global__ void __launch_bounds__(256, 3) hash_mlp_coop(
    const float*  __restrict__ fc,      // [8,16,32,32]
    const float4* __restrict__ tables,  // [8,16,T]
    const float*  __restrict__ w1, const float* __restrict__ b1,
    const float*  __restrict__ w2, const float* __restrict__ b2,
    const float*  __restrict__ w3, const float* __restrict__ b3,
    float*        __restrict__ out)     // [8,32,32,256]
{
    const int e   = blockIdx.y;
    const int tid = threadIdx.x;

    // ---- stage weights/biases for group e ----
    {
        const float* w1g = w1 + e * 4096;
        const float* w2g = w2 + e * 4096;
        const float* w3g = w3 + e * 2048;
        #pragma unroll
        for (int i = 0; i < 16; i++) smem[OFF_W1 + i * 256 + tid] = w1g[i * 256 + tid];
        #pragma unroll
        for (int i = 0; i < 16; i++) smem[OFF_W2 + i * 256 + tid] = w2g[i * 256 + tid];
        #pragma unroll
        for (int i = 0; i < 8;  i++) smem[OFF_W3 + i * 256 + tid] = w3g[i * 256 + tid];
        if (tid < 64) {
            smem[OFF_B1 + tid] = b1[e * 64 + tid];
            smem[OFF_B2 + tid] = b2[e * 64 + tid];
        } else if (tid < 96) {
            smem[OFF_B3 + tid - 64] = b3[e * 32 + (tid - 64)];
        }
    }

    // ---- phase 1: hash-grid gather+interp (4 levels per thread) ----
    const int p    = tid >> 2;      // point slot 0..63
    const int q    = tid & 3;       // level quad / neuron chunk
    const int n    = blockIdx.x * PTS + p;   // global point 0..8191
    const int b    = n >> 10;
    const int iy   = (n >> 5) & 31;
    const int ix   = n & 31;

    const float c0 = __ldg(&fc[((b * 16 + 2 * e) * 32 + iy) * 32 + ix]);
    const float c1 = __ldg(&fc[((b * 16 + 2 * e + 1) * 32 + iy) * 32 + ix]);
    const float c2 = ((float)ix + 0.5f) * (1.0f / 32.0f);
    const float c3 = ((float)iy + 0.5f) * (1.0f / 32.0f);

    const float4* tbl = tables + (size_t)e * 16 * TSIZE;
    float* frow = smem + OFF_F + p * STR;

    #pragma unroll 1
    for (int li = 0; li < 4; li++) {
        const int l = q * 4 + li;
        const float res = c_res[l];
        const float x0 = c0 * res, x1 = c1 * res, x2 = c2 * res, x3 = c3 * res;
        const float p0 = floorf(x0), p1 = floorf(x1), p2 = floorf(x2), p3 = floorf(x3);
        const float f0 = x0 - p0, f1 = x1 - p1, f2 = x2 - p2, f3 = x3 - p3;
        const float g0 = 1.f - f0, g1 = 1.f - f1, g2 = 1.f - f2, g3 = 1.f - f3;
        const uint32_t u0 = (uint32_t)p0, u1 = (uint32_t)p1,
                       u2 = (uint32_t)p2, u3 = (uint32_t)p3;

        const uint32_t a0 = u0;                 const uint32_t A0 = a0 + 1u;
        const uint32_t a1 = u1 * 2654435761u;   const uint32_t A1 = a1 + 2654435761u;
        const uint32_t a2 = u2 * 805459861u;    const uint32_t A2 = a2 + 805459861u;
        const uint32_t a3 = u3 * 3674653429u;   const uint32_t A3 = a3 + 3674653429u;

        const float4* tl = tbl + (size_t)l * TSIZE;
        float ax = 0.f, ay = 0.f, az = 0.f, aw = 0.f;
        #pragma unroll
        for (int cr = 0; cr < 16; cr++) {
            const uint32_t h = (((cr & 1) ? A0 : a0) ^ ((cr & 2) ? A1 : a1) ^
                                ((cr & 4) ? A2 : a2) ^ ((cr & 8) ? A3 : a3)) & TMASK;
            const float w = ((cr & 1) ? f0 : g0) * ((cr & 2) ? f1 : g1) *
                            ((cr & 4) ? f2 : g2) * ((cr & 8) ? f3 : g3);
            const float4 v = __ldg(&tl[h]);
            ax = fmaf(w, v.x, ax);
            ay = fmaf(w, v.y, ay);
            az = fmaf(w, v.z, az);
            aw = fmaf(w, v.w, aw);
        }
        ((float4*)frow)[l] = make_float4(ax, ay, az, aw);
    }
    __syncthreads();   // feats + weights visible

    // ---- layer 1: thread computes neurons q*16..q*16+15 ----
    float4 a0, a1, a2, a3;
    {
        const float4* bb = (const float4*)(smem + OFF_B1 + q * 16);
        a0 = bb[0]; a1 = bb[1]; a2 = bb[2]; a3 = bb[3];
        #pragma unroll
        for (int k = 0; k < 64; k += 4) {
            const float4 f = *(const float4*)(frow + k);
            #pragma unroll
            for (int kk = 0; kk < 4; kk++) {
                const float fk = (kk == 0) ? f.x : (kk == 1) ? f.y : (kk == 2) ? f.z : f.w;
                const float4* w = (const float4*)(smem + OFF_W1 + (k + kk) * 64 + q * 16);
                a0 = f4fma(fk, w[0], a0);
                a1 = f4fma(fk, w[1], a1);
                a2 = f4fma(fk, w[2], a2);
                a3 = f4fma(fk, w[3], a3);
            }
        }
    }
    __syncthreads();   // all reads of feats complete
    {
        float4* hr = (float4*)(frow + q * 16);
        hr[0] = make_float4(lrelu(a0.x), lrelu(a0.y), lrelu(a0.z), lrelu(a0.w));
        hr[1] = make_float4(lrelu(a1.x), lrelu(a1.y), lrelu(a1.z), lrelu(a1.w));
        hr[2] = make_float4(lrelu(a2.x), lrelu(a2.y), lrelu(a2.z), lrelu(a2.w));
        hr[3] = make_float4(lrelu(a3.x), lrelu(a3.y), lrelu(a3.z), lrelu(a3.w));
    }
    __syncthreads();   // h1 visible

    // ---- layer 2 ----
    {
        const float4* bb = (const float4*)(smem + OFF_B2 + q * 16);
        a0 = bb[0]; a1 = bb[1]; a2 = bb[2]; a3 = bb[3];
        #pragma unroll
        for (int k = 0; k < 64; k += 4) {
            const float4 f = *(const float4*)(frow + k);
            #pragma unroll
            for (int kk = 0; kk < 4; kk++) {
                const float fk = (kk == 0) ? f.x : (kk == 1) ? f.y : (kk == 2) ? f.z : f.w;
                const float4* w = (const float4*)(smem + OFF_W2 + (k + kk) * 64 + q * 16);
                a0 = f4fma(fk, w[0], a0);
                a1 = f4fma(fk, w[1], a1);
                a2 = f4fma(fk, w[2], a2);
                a3 = f4fma(fk, w[3], a3);
            }
        }
    }
    __syncthreads();   // all reads of h1 complete
    {
        float4* hr = (float4*)(frow + q * 16);
        hr[0] = make_float4(lrelu(a0.x), lrelu(a0.y), lrelu(a0.z), lrelu(a0.w));
        hr[1] = make_float4(lrelu(a1.x), lrelu(a1.y), lrelu(a1.z), lrelu(a1.w));
        hr[2] = make_float4(lrelu(a2.x), lrelu(a2.y), lrelu(a2.z), lrelu(a2.w));
        hr[3] = make_float4(lrelu(a3.x), lrelu(a3.y), lrelu(a3.z), lrelu(a3.w));
    }
    __syncthreads();   // h2 visible

    // ---- layer 3: thread computes outputs q*8..q*8+7, writes gmem ----
    {
        const float4* bb = (const float4*)(smem + OFF_B3 + q * 8);
        a0 = bb[0]; a1 = bb[1];
        #pragma unroll
        for (int k = 0; k < 64; k += 4) {
            const float4 f = *(const float4*)(frow + k);
            #pragma unroll
            for (int kk = 0; kk < 4; kk++) {
                const float fk = (kk == 0) ? f.x : (kk == 1) ? f.y : (kk == 2) ? f.z : f.w;
                const float4* w = (const float4*)(smem + OFF_W3 + (k + kk) * 32 + q * 8);
                a0 = f4fma(fk, w[0], a0);
                a1 = f4fma(fk, w[1], a1);
            }
        }
        float4* op = (float4*)(out + (size_t)n * 256 + e * 32 + q * 8);
        op[0] = a0;
        op[1] = a1;
    }
}

extern "C" void kernel_launch(void* const* d_in, const int* in_sizes, int n_in,
                              void* d_out, int out_size) {
    const float*  fc     = (const float*)d_in[0];
    const float4* tables = (const float4*)d_in[1];
    const float*  w1     = (const float*)d_in[2];
    const float*  b1     = (const float*)d_in[3];
    const float*  w2     = (const float*)d_in[4];
    const float*  b2     = (const float*)d_in[5];
    const float*  w3     = (const float*)d_in[6];
    const float*  b3     = (const float*)d_in[7];

    const int smem_bytes = SMEM_FLOATS * sizeof(float);   // ~59 KB
    static bool configured = false;
    if (!configured) {
        cudaFuncSetAttribute(hash_mlp_coop,
                             cudaFuncAttributeMaxDynamicSharedMemorySize, smem_bytes);
        configured = true;
    }

    dim3 grid(8192 / PTS, 8);   // (128, 8)
    hash_mlp_coop<<<grid, 256, smem_bytes>>>(fc, tables, w1, b1, w2, b2, w3, b3,
                                             (float*)d_out);
}

// round 5
// speedup vs baseline: 1.4433x; 1.4433x over previous
#include <cuda_runtime.h>
#include <cstdint>

// B=8,R=32 -> 8192 points; E=8 groups; L=16 levels; F=4; T=2^17
// MLP 64->64->64->32, leaky_relu(0.2)
// Thread-per-point, broadcast weight reads from shared, h1 + o in registers.
// Layer 2 evaluated neuron-at-a-time (transposed w2) and folded straight into o[32].

#define TMASK 0x1FFFFu
#define TSIZE (1u << 17)

__constant__ float c_res[16] = {16.f,16.f,17.f,18.f,19.f,20.f,21.f,22.f,
                                23.f,24.f,25.f,26.f,27.f,29.f,30.f,32.f};

__device__ __forceinline__ float lrelu(float v) { return v > 0.f ? v : 0.2f * v; }

__global__ void __launch_bounds__(128, 4) hash_mlp_r4(
    const float*  __restrict__ fc,      // [8,16,32,32]
    const float4* __restrict__ tables,  // [8,16,T]
    const float*  __restrict__ w1, const float* __restrict__ b1,
    const float*  __restrict__ w2, const float* __restrict__ b2,
    const float*  __restrict__ w3, const float* __restrict__ b3,
    float*        __restrict__ out)     // [8,32,32,256]
{
    __shared__ __align__(16) float s_w1[64 * 64];    // row-major [k][j]
    __shared__ __align__(16) float s_w2t[64 * 64];   // TRANSPOSED: [j][k]
    __shared__ __align__(16) float s_w3[64 * 32];    // row-major [j][i]
    __shared__ float s_b2[64], s_b3[32];
    __shared__ float s_b1v[64];

    const int e   = blockIdx.y;
    const int tid = threadIdx.x;

    // ---- stage weights (w2 transposed) ----
    {
        const float* w1g = w1 + e * 4096;
        const float* w2g = w2 + e * 4096;
        const float* w3g = w3 + e * 2048;
        #pragma unroll
        for (int i = 0; i < 32; i++) s_w1[i * 128 + tid] = w1g[i * 128 + tid];
        #pragma unroll
        for (int i = 0; i < 32; i++) {
            const int f = i * 128 + tid;            // flat idx: k = f>>6, j = f&63
            s_w2t[(f & 63) * 64 + (f >> 6)] = w2g[f];
        }
        #pragma unroll
        for (int i = 0; i < 16; i++) s_w3[i * 128 + tid] = w3g[i * 128 + tid];
        if (tid < 64) {
            s_b1v[tid] = b1[e * 64 + tid];
            s_b2[tid]  = b2[e * 64 + tid];
        } else if (tid < 96) {
            s_b3[tid - 64] = b3[e * 32 + (tid - 64)];
        }
    }
    __syncthreads();

    const int n  = blockIdx.x * 128 + tid;      // point id 0..8191
    const int b  = n >> 10;
    const int iy = (n >> 5) & 31;
    const int ix = n & 31;

    const float c0 = __ldg(&fc[((b * 16 + 2 * e) * 32 + iy) * 32 + ix]);
    const float c1 = __ldg(&fc[((b * 16 + 2 * e + 1) * 32 + iy) * 32 + ix]);
    const float c2 = ((float)ix + 0.5f) * (1.0f / 32.0f);
    const float c3 = ((float)iy + 0.5f) * (1.0f / 32.0f);

    const float4* tbl = tables + (size_t)e * 16 * TSIZE;

    float h1[64];
    #pragma unroll
    for (int j = 0; j < 64; j++) h1[j] = s_b1v[j];

    #pragma unroll 1
    for (int l = 0; l < 16; l++) {
        const float res = c_res[l];
        const float x0 = c0 * res, x1 = c1 * res, x2 = c2 * res, x3 = c3 * res;
        const float p0 = floorf(x0), p1 = floorf(x1), p2 = floorf(x2), p3 = floorf(x3);
        const float f0 = x0 - p0, f1 = x1 - p1, f2 = x2 - p2, f3 = x3 - p3;
        const float g0 = 1.f - f0, g1 = 1.f - f1, g2 = 1.f - f2, g3 = 1.f - f3;
        const uint32_t u0 = (uint32_t)p0, u1 = (uint32_t)p1,
                       u2 = (uint32_t)p2, u3 = (uint32_t)p3;

        const uint32_t a0 = u0;                 const uint32_t A0 = a0 + 1u;
        const uint32_t a1 = u1 * 2654435761u;   const uint32_t A1 = a1 + 2654435761u;
        const uint32_t a2 = u2 * 805459861u;    const uint32_t A2 = a2 + 805459861u;
        const uint32_t a3 = u3 * 3674653429u;   const uint32_t A3 = a3 + 3674653429u;

        const float4* tl = tbl + (size_t)l * TSIZE;

        float acc0 = 0.f, acc1 = 0.f, acc2 = 0.f, acc3 = 0.f;
        // two batches of 8 corners: caps in-flight LDG dest registers at 32
        #pragma unroll
        for (int half = 0; half < 2; half++) {
            float4 v[8];
            float  wg[8];
            #pragma unroll
            for (int c8 = 0; c8 < 8; c8++) {
                const int cr = half * 8 + c8;
                const uint32_t h = (((cr & 1) ? A0 : a0) ^ ((cr & 2) ? A1 : a1) ^
                                    ((cr & 4) ? A2 : a2) ^ ((cr & 8) ? A3 : a3)) & TMASK;
                wg[c8] = ((cr & 1) ? f0 : g0) * ((cr & 2) ? f1 : g1) *
                         ((cr & 4) ? f2 : g2) * ((cr & 8) ? f3 : g3);
                v[c8] = __ldg(&tl[h]);
            }
            #pragma unroll
            for (int c8 = 0; c8 < 8; c8++) {
                acc0 = fmaf(wg[c8], v[c8].x, acc0);
                acc1 = fmaf(wg[c8], v[c8].y, acc1);
                acc2 = fmaf(wg[c8], v[c8].z, acc2);
                acc3 = fmaf(wg[c8], v[c8].w, acc3);
            }
        }

        // fold level features into h1 (broadcast weight reads)
        const float4* wl = (const float4*)(s_w1 + l * 4 * 64);
        #pragma unroll
        for (int j = 0; j < 16; j++) {
            const float4 wa = wl[j];
            const float4 wb = wl[16 + j];
            const float4 wc = wl[32 + j];
            const float4 wd = wl[48 + j];
            h1[4*j+0] = fmaf(acc0, wa.x, fmaf(acc1, wb.x, fmaf(acc2, wc.x, fmaf(acc3, wd.x, h1[4*j+0]))));
            h1[4*j+1] = fmaf(acc0, wa.y, fmaf(acc1, wb.y, fmaf(acc2, wc.y, fmaf(acc3, wd.y, h1[4*j+1]))));
            h1[4*j+2] = fmaf(acc0, wa.z, fmaf(acc1, wb.z, fmaf(acc2, wc.z, fmaf(acc3, wd.z, h1[4*j+2]))));
            h1[4*j+3] = fmaf(acc0, wa.w, fmaf(acc1, wb.w, fmaf(acc2, wc.w, fmaf(acc3, wd.w, h1[4*j+3]))));
        }
    }

    #pragma unroll
    for (int k = 0; k < 64; k++) h1[k] = lrelu(h1[k]);

    // ---- layers 2+3 fused: neuron-at-a-time, fold into o[32] ----
    float o[32];
    #pragma unroll
    for (int i = 0; i < 8; i++) ((float4*)o)[i] = ((const float4*)s_b3)[i];

    #pragma unroll 4
    for (int j = 0; j < 64; j++) {
        float acc = s_b2[j];
        const float4* wt = (const float4*)(s_w2t + j * 64);
        #pragma unroll
        for (int t = 0; t < 16; t++) {
            const float4 w = wt[t];
            acc = fmaf(h1[4*t+0], w.x, acc);
            acc = fmaf(h1[4*t+1], w.y, acc);
            acc = fmaf(h1[4*t+2], w.z, acc);
            acc = fmaf(h1[4*t+3], w.w, acc);
        }
        const float a = lrelu(acc);
        const float4* w3r = (const float4*)(s_w3 + j * 32);
        #pragma unroll
        for (int t = 0; t < 8; t++) {
            const float4 w = w3r[t];
            o[4*t+0] = fmaf(a, w.x, o[4*t+0]);
            o[4*t+1] = fmaf(a, w.y, o[4*t+1]);
            o[4*t+2] = fmaf(a, w.z, o[4*t+2]);
            o[4*t+3] = fmaf(a, w.w, o[4*t+3]);
        }
    }

    float4* op = (float4*)(out + (size_t)n * 256 + e * 32);
    #pragma unroll
    for (int t = 0; t < 8; t++) op[t] = ((float4*)o)[t];
}

extern "C" void kernel_launch(void* const* d_in, const int* in_sizes, int n_in,
                              void* d_out, int out_size) {
    const float*  fc     = (const float*)d_in[0];
    const float4* tables = (const float4*)d_in[1];
    const float*  w1     = (const float*)d_in[2];
    const float*  b1     = (const float*)d_in[3];
    const float*  w2     = (const float*)d_in[4];
    const float*  b2     = (const float*)d_in[5];
    const float*  w3     = (const float*)d_in[6];
    const float*  b3     = (const float*)d_in[7];

    dim3 grid(64, 8);   // 512 CTAs -> single wave at 4 CTAs/SM
    hash_mlp_r4<<<grid, 128>>>(fc, tables, w1, b1, w2, b2, w3, b3, (float*)d_out);
}

// round 7
// speedup vs baseline: 1.4462x; 1.0020x over previous
#include <cuda_runtime.h>
#include <cstdint>

// B=8,R=32 -> 8192 points; E=8 groups; L=16 levels; F=4; T=2^17
// MLP 64->64->64->32, leaky_relu(0.2)
// Thread-per-point, broadcast weight reads from shared, h1 + o in registers.
// Layer 2 evaluated neuron-at-a-time (transposed w2) and folded straight into o[32].

#define TMASK 0x1FFFFu
#define TSIZE (1u << 17)

__constant__ float c_res[16] = {16.f,16.f,17.f,18.f,19.f,20.f,21.f,22.f,
                                23.f,24.f,25.f,26.f,27.f,29.f,30.f,32.f};

__device__ __forceinline__ float lrelu(float v) { return v > 0.f ? v : 0.2f * v; }

__global__ void __launch_bounds__(128, 4) hash_mlp_r4(
    const float*  __restrict__ fc,      // [8,16,32,32]
    const float4* __restrict__ tables,  // [8,16,T]
    const float*  __restrict__ w1, const float* __restrict__ b1,
    const float*  __restrict__ w2, const float* __restrict__ b2,
    const float*  __restrict__ w3, const float* __restrict__ b3,
    float*        __restrict__ out)     // [8,32,32,256]
{
    __shared__ __align__(16) float s_w1[64 * 64];    // row-major [k][j]
    __shared__ __align__(16) float s_w2t[64 * 64];   // TRANSPOSED: [j][k]
    __shared__ __align__(16) float s_w3[64 * 32];    // row-major [j][i]
    __shared__ float s_b2[64], s_b3[32];
    __shared__ float s_b1v[64];

    const int e   = blockIdx.y;
    const int tid = threadIdx.x;

    // ---- stage weights (w2 transposed) ----
    {
        const float* w1g = w1 + e * 4096;
        const float* w2g = w2 + e * 4096;
        const float* w3g = w3 + e * 2048;
        #pragma unroll
        for (int i = 0; i < 32; i++) s_w1[i * 128 + tid] = w1g[i * 128 + tid];
        #pragma unroll
        for (int i = 0; i < 32; i++) {
            const int f = i * 128 + tid;            // flat idx: k = f>>6, j = f&63
            s_w2t[(f & 63) * 64 + (f >> 6)] = w2g[f];
        }
        #pragma unroll
        for (int i = 0; i < 16; i++) s_w3[i * 128 + tid] = w3g[i * 128 + tid];
        if (tid < 64) {
            s_b1v[tid] = b1[e * 64 + tid];
            s_b2[tid]  = b2[e * 64 + tid];
        } else if (tid < 96) {
            s_b3[tid - 64] = b3[e * 32 + (tid - 64)];
        }
    }
    __syncthreads();

    const int n  = blockIdx.x * 128 + tid;      // point id 0..8191
    const int b  = n >> 10;
    const int iy = (n >> 5) & 31;
    const int ix = n & 31;

    const float c0 = __ldg(&fc[((b * 16 + 2 * e) * 32 + iy) * 32 + ix]);
    const float c1 = __ldg(&fc[((b * 16 + 2 * e + 1) * 32 + iy) * 32 + ix]);
    const float c2 = ((float)ix + 0.5f) * (1.0f / 32.0f);
    const float c3 = ((float)iy + 0.5f) * (1.0f / 32.0f);

    const float4* tbl = tables + (size_t)e * 16 * TSIZE;

    float h1[64];
    #pragma unroll
    for (int j = 0; j < 64; j++) h1[j] = s_b1v[j];

    #pragma unroll 1
    for (int l = 0; l < 16; l++) {
        const float res = c_res[l];
        const float x0 = c0 * res, x1 = c1 * res, x2 = c2 * res, x3 = c3 * res;
        const float p0 = floorf(x0), p1 = floorf(x1), p2 = floorf(x2), p3 = floorf(x3);
        const float f0 = x0 - p0, f1 = x1 - p1, f2 = x2 - p2, f3 = x3 - p3;
        const float g0 = 1.f - f0, g1 = 1.f - f1, g2 = 1.f - f2, g3 = 1.f - f3;
        const uint32_t u0 = (uint32_t)p0, u1 = (uint32_t)p1,
                       u2 = (uint32_t)p2, u3 = (uint32_t)p3;

        const uint32_t a0 = u0;                 const uint32_t A0 = a0 + 1u;
        const uint32_t a1 = u1 * 2654435761u;   const uint32_t A1 = a1 + 2654435761u;
        const uint32_t a2 = u2 * 805459861u;    const uint32_t A2 = a2 + 805459861u;
        const uint32_t a3 = u3 * 3674653429u;   const uint32_t A3 = a3 + 3674653429u;

        const float4* tl = tbl + (size_t)l * TSIZE;

        float acc0 = 0.f, acc1 = 0.f, acc2 = 0.f, acc3 = 0.f;
        // two batches of 8 corners: caps in-flight LDG dest registers at 32
        #pragma unroll
        for (int half = 0; half < 2; half++) {
            float4 v[8];
            float  wg[8];
            #pragma unroll
            for (int c8 = 0; c8 < 8; c8++) {
                const int cr = half * 8 + c8;
                const uint32_t h = (((cr & 1) ? A0 : a0) ^ ((cr & 2) ? A1 : a1) ^
                                    ((cr & 4) ? A2 : a2) ^ ((cr & 8) ? A3 : a3)) & TMASK;
                wg[c8] = ((cr & 1) ? f0 : g0) * ((cr & 2) ? f1 : g1) *
                         ((cr & 4) ? f2 : g2) * ((cr & 8) ? f3 : g3);
                v[c8] = __ldg(&tl[h]);
            }
            #pragma unroll
            for (int c8 = 0; c8 < 8; c8++) {
                acc0 = fmaf(wg[c8], v[c8].x, acc0);
                acc1 = fmaf(wg[c8], v[c8].y, acc1);
                acc2 = fmaf(wg[c8], v[c8].z, acc2);
                acc3 = fmaf(wg[c8], v[c8].w, acc3);
            }
        }

        // fold level features into h1 (broadcast weight reads)
        const float4* wl = (const float4*)(s_w1 + l * 4 * 64);
        #pragma unroll
        for (int j = 0; j < 16; j++) {
            const float4 wa = wl[j];
            const float4 wb = wl[16 + j];
            const float4 wc = wl[32 + j];
            const float4 wd = wl[48 + j];
            h1[4*j+0] = fmaf(acc0, wa.x, fmaf(acc1, wb.x, fmaf(acc2, wc.x, fmaf(acc3, wd.x, h1[4*j+0]))));
            h1[4*j+1] = fmaf(acc0, wa.y, fmaf(acc1, wb.y, fmaf(acc2, wc.y, fmaf(acc3, wd.y, h1[4*j+1]))));
            h1[4*j+2] = fmaf(acc0, wa.z, fmaf(acc1, wb.z, fmaf(acc2, wc.z, fmaf(acc3, wd.z, h1[4*j+2]))));
            h1[4*j+3] = fmaf(acc0, wa.w, fmaf(acc1, wb.w, fmaf(acc2, wc.w, fmaf(acc3, wd.w, h1[4*j+3]))));
        }
    }

    #pragma unroll
    for (int k = 0; k < 64; k++) h1[k] = lrelu(h1[k]);

    // ---- layers 2+3 fused: neuron-at-a-time, fold into o[32] ----
    float o[32];
    #pragma unroll
    for (int i = 0; i < 8; i++) ((float4*)o)[i] = ((const float4*)s_b3)[i];

    #pragma unroll 4
    for (int j = 0; j < 64; j++) {
        float acc = s_b2[j];
        const float4* wt = (const float4*)(s_w2t + j * 64);
        #pragma unroll
        for (int t = 0; t < 16; t++) {
            const float4 w = wt[t];
            acc = fmaf(h1[4*t+0], w.x, acc);
            acc = fmaf(h1[4*t+1], w.y, acc);
            acc = fmaf(h1[4*t+2], w.z, acc);
            acc = fmaf(h1[4*t+3], w.w, acc);
        }
        const float a = lrelu(acc);
        const float4* w3r = (const float4*)(s_w3 + j * 32);
        #pragma unroll
        for (int t = 0; t < 8; t++) {
            const float4 w = w3r[t];
            o[4*t+0] = fmaf(a, w.x, o[4*t+0]);
            o[4*t+1] = fmaf(a, w.y, o[4*t+1]);
            o[4*t+2] = fmaf(a, w.z, o[4*t+2]);
            o[4*t+3] = fmaf(a, w.w, o[4*t+3]);
        }
    }

    float4* op = (float4*)(out + (size_t)n * 256 + e * 32);
    #pragma unroll
    for (int t = 0; t < 8; t++) op[t] = ((float4*)o)[t];
}

extern "C" void kernel_launch(void* const* d_in, const int* in_sizes, int n_in,
                              void* d_out, int out_size) {
    const float*  fc     = (const float*)d_in[0];
    const float4* tables = (const float4*)d_in[1];
    const float*  w1     = (const float*)d_in[2];
    const float*  b1     = (const float*)d_in[3];
    const float*  w2     = (const float*)d_in[4];
    const float*  b2     = (const float*)d_in[5];
    const float*  w3     = (const float*)d_in[6];
    const float*  b3     = (const float*)d_in[7];

    dim3 grid(64, 8);   // 512 CTAs -> single wave at 4 CTAs/SM
    hash_mlp_r4<<<grid, 128>>>(fc, tables, w1, b1, w2, b2, w3, b3, (float*)d_out);
}